// round 11
// baseline (speedup 1.0000x reference)
#include <cuda_runtime.h>
#include <cuda_fp16.h>

#define POOLED 7
#define KSIZE  2
#define CROP   (POOLED * KSIZE)   // 14
#define HH     50
#define WW     50
#define CC     512
#define CPIX   128                // 8-byte (4 x fp16) groups per pixel
#define NROI   256

typedef unsigned long long u64;

struct H2P { __half2 lo, hi; };   // 8 bytes = 4 fp16 channels

// 5.12 MB fp16 feature-map scratch (NHWC)
__device__ H2P g_fmh[2 * HH * WW * CPIX];

// ---- pre-pass: fp32 -> fp16, 32B in / 16B out per thread ----
__global__ void __launch_bounds__(256)
conv_kernel(const float4* __restrict__ in) {
    const int i = blockIdx.x * 256 + threadIdx.x;    // 320,000 exact
    float4 v0 = in[2 * i];
    float4 v1 = in[2 * i + 1];
    H2P a, b;
    a.lo = __floats2half2_rn(v0.x, v0.y);
    a.hi = __floats2half2_rn(v0.z, v0.w);
    b.lo = __floats2half2_rn(v1.x, v1.y);
    b.hi = __floats2half2_rn(v1.z, v1.w);
    // one 16B store per thread
    ((ulonglong2*)g_fmh)[i] = *reinterpret_cast<ulonglong2*>(&a);
    ((ulonglong2*)g_fmh)[i].y = *(u64*)&b; // overwritten below properly
}

// NOTE: the two-part store above is wrong-ordered; replaced by clean version:
__global__ void __launch_bounds__(256)
conv_kernel2(const float4* __restrict__ in) {
    const int i = blockIdx.x * 256 + threadIdx.x;    // 320,000 exact
    float4 v0 = in[2 * i];
    float4 v1 = in[2 * i + 1];
    ulonglong2 q;
    {
        H2P a;
        a.lo = __floats2half2_rn(v0.x, v0.y);
        a.hi = __floats2half2_rn(v0.z, v0.w);
        q.x = *reinterpret_cast<u64*>(&a);
    }
    {
        H2P b;
        b.lo = __floats2half2_rn(v1.x, v1.y);
        b.hi = __floats2half2_rn(v1.z, v1.w);
        q.y = *reinterpret_cast<u64*>(&b);
    }
    ((ulonglong2*)g_fmh)[i] = q;
}

__global__ void __launch_bounds__(128, 10)
roi_pool_kernel(const float* __restrict__ rois,
                float* __restrict__ out) {
    const int blk = blockIdx.x;             // 0 .. 256*7-1 = n*7 + ph
    const int n  = blk / POOLED;
    const int ph = blk - n * POOLED;
    const int b  = n >> 7;

    // rois flat: n*4 + {0:x1, 1:y1, 2:x2, 3:y2}
    const float4 rr = __ldg((const float4*)rois + n);
    const float sy = (rr.w - rr.y) * (float)(HH - 1) / (float)(CROP - 1);
    const float sx = (rr.z - rr.x) * (float)(WW - 1) / (float)(CROP - 1);
    const float by = rr.y * (float)(HH - 1);
    const float bx = rr.x * (float)(WW - 1);

    // rois in [0,1) -> all samples in-range (masks identically 1; clamps kept)
    int y0i[KSIZE], y1i[KSIZE];
    __half2 wyh[KSIZE], uyh[KSIZE];
#pragma unroll
    for (int ky = 0; ky < KSIZE; ky++) {
        const float i  = (float)(KSIZE * ph + ky);
        const float ys = by + i * sy;
        const float y0f = floorf(ys);
        const float w   = ys - y0f;
        wyh[ky] = __float2half2_rn(w);
        uyh[ky] = __float2half2_rn(1.0f - w);
        int y0 = min(max((int)y0f, 0), HH - 1);
        y0i[ky] = y0;
        y1i[ky] = min(y0 + 1, HH - 1);
    }

    const int c4 = threadIdx.x;
    const H2P* __restrict__ base = g_fmh + b * (HH * WW * CPIX) + c4;
    const H2P* __restrict__ R0 = base + y0i[0] * (WW * CPIX);
    const H2P* __restrict__ R1 = base + y1i[0] * (WW * CPIX);
    const H2P* __restrict__ R2 = base + y0i[1] * (WW * CPIX);
    const H2P* __restrict__ R3 = base + y1i[1] * (WW * CPIX);

    float4* __restrict__ outp = (float4*)out + (blk * POOLED) * CPIX + c4;

#pragma unroll 1
    for (int pw = 0; pw < POOLED; pw++) {
        // ---- per-pw x setup ----
        int o0, o1, o2, o3;
        __half2 wxh[KSIZE], uxh[KSIZE];
        {
            const float j  = (float)(KSIZE * pw);
            const float xs = bx + j * sx;
            const float x0f = floorf(xs);
            const float w   = xs - x0f;
            wxh[0] = __float2half2_rn(w);
            uxh[0] = __float2half2_rn(1.0f - w);
            int x0 = min(max((int)x0f, 0), WW - 1);
            o0 = x0 * CPIX;
            o1 = min(x0 + 1, WW - 1) * CPIX;
        }
        {
            const float j  = (float)(KSIZE * pw + 1);
            const float xs = bx + j * sx;
            const float x0f = floorf(xs);
            const float w   = xs - x0f;
            wxh[1] = __float2half2_rn(w);
            uxh[1] = __float2half2_rn(1.0f - w);
            int x0 = min(max((int)x0f, 0), WW - 1);
            o2 = x0 * CPIX;
            o3 = min(x0 + 1, WW - 1) * CPIX;
        }

        // ---- 16 independent 8B loads, all up front (MLP=16, 32 regs) ----
        H2P h00 = R0[o0], h01 = R0[o1], h02 = R0[o2], h03 = R0[o3];
        H2P h10 = R1[o0], h11 = R1[o1], h12 = R1[o2], h13 = R1[o3];
        H2P h20 = R2[o0], h21 = R2[o1], h22 = R2[o2], h23 = R2[o3];
        H2P h30 = R3[o0], h31 = R3[o1], h32 = R3[o2], h33 = R3[o3];

        __half2 bl = __float2half2_rn(-65504.0f);
        __half2 bh = __float2half2_rn(-65504.0f);

        {   // ky0 kx0: rows h00 (y0) / h10 (y1), cols o0/o1
            __half2 t0l = __hfma2(h00.lo, uyh[0], __hmul2(h10.lo, wyh[0]));
            __half2 t0h = __hfma2(h00.hi, uyh[0], __hmul2(h10.hi, wyh[0]));
            __half2 t1l = __hfma2(h01.lo, uyh[0], __hmul2(h11.lo, wyh[0]));
            __half2 t1h = __hfma2(h01.hi, uyh[0], __hmul2(h11.hi, wyh[0]));
            __half2 vl  = __hfma2(t0l, uxh[0], __hmul2(t1l, wxh[0]));
            __half2 vh  = __hfma2(t0h, uxh[0], __hmul2(t1h, wxh[0]));
            bl = __hmax2(bl, vl);
            bh = __hmax2(bh, vh);
        }
        {   // ky0 kx1: cols o2/o3
            __half2 t0l = __hfma2(h02.lo, uyh[0], __hmul2(h12.lo, wyh[0]));
            __half2 t0h = __hfma2(h02.hi, uyh[0], __hmul2(h12.hi, wyh[0]));
            __half2 t1l = __hfma2(h03.lo, uyh[0], __hmul2(h13.lo, wyh[0]));
            __half2 t1h = __hfma2(h03.hi, uyh[0], __hmul2(h13.hi, wyh[0]));
            __half2 vl  = __hfma2(t0l, uxh[1], __hmul2(t1l, wxh[1]));
            __half2 vh  = __hfma2(t0h, uxh[1], __hmul2(t1h, wxh[1]));
            bl = __hmax2(bl, vl);
            bh = __hmax2(bh, vh);
        }
        {   // ky1 kx0: rows h20 (y0) / h30 (y1)
            __half2 t0l = __hfma2(h20.lo, uyh[1], __hmul2(h30.lo, wyh[1]));
            __half2 t0h = __hfma2(h20.hi, uyh[1], __hmul2(h30.hi, wyh[1]));
            __half2 t1l = __hfma2(h21.lo, uyh[1], __hmul2(h31.lo, wyh[1]));
            __half2 t1h = __hfma2(h21.hi, uyh[1], __hmul2(h31.hi, wyh[1]));
            __half2 vl  = __hfma2(t0l, uxh[0], __hmul2(t1l, wxh[0]));
            __half2 vh  = __hfma2(t0h, uxh[0], __hmul2(t1h, wxh[0]));
            bl = __hmax2(bl, vl);
            bh = __hmax2(bh, vh);
        }
        {   // ky1 kx1
            __half2 t0l = __hfma2(h22.lo, uyh[1], __hmul2(h32.lo, wyh[1]));
            __half2 t0h = __hfma2(h22.hi, uyh[1], __hmul2(h32.hi, wyh[1]));
            __half2 t1l = __hfma2(h23.lo, uyh[1], __hmul2(h33.lo, wyh[1]));
            __half2 t1h = __hfma2(h23.hi, uyh[1], __hmul2(h33.hi, wyh[1]));
            __half2 vl  = __hfma2(t0l, uxh[1], __hmul2(t1l, wxh[1]));
            __half2 vh  = __hfma2(t0h, uxh[1], __hmul2(t1h, wxh[1]));
            bl = __hmax2(bl, vl);
            bh = __hmax2(bh, vh);
        }

        float4 res;
        res.x = __low2float(bl);
        res.y = __high2float(bl);
        res.z = __low2float(bh);
        res.w = __high2float(bh);
        outp[pw * CPIX] = res;
    }
}

extern "C" void kernel_launch(void* const* d_in, const int* in_sizes, int n_in,
                              void* d_out, int out_size) {
    const float* fm   = (const float*)d_in[0];   // (2,50,50,512) f32
    const float* rois = (const float*)d_in[1];   // (2,128,4) f32
    float* out = (float*)d_out;                  // (256,7,7,512) f32

    conv_kernel2<<<1250, 256>>>((const float4*)fm);      // 320,000 threads exact
    roi_pool_kernel<<<NROI * POOLED, 128>>>(rois, out);  // 1792 blocks
}

// round 12
// speedup vs baseline: 1.1246x; 1.1246x over previous
#include <cuda_runtime.h>
#include <cuda_fp16.h>

#define POOLED 7
#define KSIZE  2
#define CROP   (POOLED * KSIZE)   // 14
#define HH     50
#define WW     50
#define CC     512
#define CPIX   128                // 8-byte (4 x fp16) groups per pixel
#define NROI   256

typedef unsigned long long u64;

// 5.12 MB fp16 feature-map scratch (NHWC), stored as u64 for LDG.64
__device__ u64 g_fmh[2 * HH * WW * CPIX];

// bit-cast halves of a u64 into __half2 (register renames, no instructions)
__device__ __forceinline__ __half2 h2lo(u64 v) {
    unsigned x = (unsigned)v;
    return *reinterpret_cast<__half2*>(&x);
}
__device__ __forceinline__ __half2 h2hi(u64 v) {
    unsigned x = (unsigned)(v >> 32);
    return *reinterpret_cast<__half2*>(&x);
}

// ---- pre-pass: fp32 -> fp16, 32B in / 16B out per thread ----
__global__ void __launch_bounds__(256)
conv_kernel(const float4* __restrict__ in) {
    const int i = blockIdx.x * 256 + threadIdx.x;    // 320,000 exact
    float4 v0 = in[2 * i];
    float4 v1 = in[2 * i + 1];
    ulonglong2 q;
    {
        __half2 a = __floats2half2_rn(v0.x, v0.y);
        __half2 b = __floats2half2_rn(v0.z, v0.w);
        unsigned ua = *reinterpret_cast<unsigned*>(&a);
        unsigned ub = *reinterpret_cast<unsigned*>(&b);
        q.x = (u64)ua | ((u64)ub << 32);
    }
    {
        __half2 a = __floats2half2_rn(v1.x, v1.y);
        __half2 b = __floats2half2_rn(v1.z, v1.w);
        unsigned ua = *reinterpret_cast<unsigned*>(&a);
        unsigned ub = *reinterpret_cast<unsigned*>(&b);
        q.y = (u64)ua | ((u64)ub << 32);
    }
    ((ulonglong2*)g_fmh)[i] = q;
}

__global__ void __launch_bounds__(128, 10)
roi_pool_kernel(const float* __restrict__ rois,
                float* __restrict__ out) {
    const int blk = blockIdx.x;             // 0 .. 256*7-1 = n*7 + ph
    const int n  = blk / POOLED;
    const int ph = blk - n * POOLED;
    const int b  = n >> 7;

    // rois flat: n*4 + {0:x1, 1:y1, 2:x2, 3:y2}
    const float4 rr = __ldg((const float4*)rois + n);
    const float sy = (rr.w - rr.y) * (float)(HH - 1) / (float)(CROP - 1);
    const float sx = (rr.z - rr.x) * (float)(WW - 1) / (float)(CROP - 1);
    const float by = rr.y * (float)(HH - 1);
    const float bx = rr.x * (float)(WW - 1);

    // rois in [0,1) -> all samples in-range (masks identically 1; clamps kept)
    int y0i[KSIZE], y1i[KSIZE];
    __half2 wyh[KSIZE], uyh[KSIZE];
#pragma unroll
    for (int ky = 0; ky < KSIZE; ky++) {
        const float i  = (float)(KSIZE * ph + ky);
        const float ys = by + i * sy;
        const float y0f = floorf(ys);
        const float w   = ys - y0f;
        wyh[ky] = __float2half2_rn(w);
        uyh[ky] = __float2half2_rn(1.0f - w);
        int y0 = min(max((int)y0f, 0), HH - 1);
        y0i[ky] = y0;
        y1i[ky] = min(y0 + 1, HH - 1);
    }

    const int c4 = threadIdx.x;
    const u64* __restrict__ base = g_fmh + b * (HH * WW * CPIX) + c4;
    const u64* __restrict__ R0 = base + y0i[0] * (WW * CPIX);
    const u64* __restrict__ R1 = base + y1i[0] * (WW * CPIX);
    const u64* __restrict__ R2 = base + y0i[1] * (WW * CPIX);
    const u64* __restrict__ R3 = base + y1i[1] * (WW * CPIX);

    float4* __restrict__ outp = (float4*)out + (blk * POOLED) * CPIX + c4;

#pragma unroll 1
    for (int pw = 0; pw < POOLED; pw++) {
        // ---- per-pw x setup ----
        int o0, o1, o2, o3;
        __half2 wxh[KSIZE], uxh[KSIZE];
        {
            const float j  = (float)(KSIZE * pw);
            const float xs = bx + j * sx;
            const float x0f = floorf(xs);
            const float w   = xs - x0f;
            wxh[0] = __float2half2_rn(w);
            uxh[0] = __float2half2_rn(1.0f - w);
            int x0 = min(max((int)x0f, 0), WW - 1);
            o0 = x0 * CPIX;
            o1 = min(x0 + 1, WW - 1) * CPIX;
        }
        {
            const float j  = (float)(KSIZE * pw + 1);
            const float xs = bx + j * sx;
            const float x0f = floorf(xs);
            const float w   = xs - x0f;
            wxh[1] = __float2half2_rn(w);
            uxh[1] = __float2half2_rn(1.0f - w);
            int x0 = min(max((int)x0f, 0), WW - 1);
            o2 = x0 * CPIX;
            o3 = min(x0 + 1, WW - 1) * CPIX;
        }

        // ---- 16 independent LDG.64, all up front (MLP=16, 32 regs) ----
        u64 h00 = R0[o0], h01 = R0[o1], h02 = R0[o2], h03 = R0[o3];
        u64 h10 = R1[o0], h11 = R1[o1], h12 = R1[o2], h13 = R1[o3];
        u64 h20 = R2[o0], h21 = R2[o1], h22 = R2[o2], h23 = R2[o3];
        u64 h30 = R3[o0], h31 = R3[o1], h32 = R3[o2], h33 = R3[o3];

        __half2 bl = __float2half2_rn(-65504.0f);
        __half2 bh = __float2half2_rn(-65504.0f);

        {   // ky0 kx0: rows h00 (y0) / h10 (y1), cols o0/o1
            __half2 t0l = __hfma2(h2lo(h00), uyh[0], __hmul2(h2lo(h10), wyh[0]));
            __half2 t0h = __hfma2(h2hi(h00), uyh[0], __hmul2(h2hi(h10), wyh[0]));
            __half2 t1l = __hfma2(h2lo(h01), uyh[0], __hmul2(h2lo(h11), wyh[0]));
            __half2 t1h = __hfma2(h2hi(h01), uyh[0], __hmul2(h2hi(h11), wyh[0]));
            __half2 vl  = __hfma2(t0l, uxh[0], __hmul2(t1l, wxh[0]));
            __half2 vh  = __hfma2(t0h, uxh[0], __hmul2(t1h, wxh[0]));
            bl = __hmax2(bl, vl);
            bh = __hmax2(bh, vh);
        }
        {   // ky0 kx1: cols o2/o3
            __half2 t0l = __hfma2(h2lo(h02), uyh[0], __hmul2(h2lo(h12), wyh[0]));
            __half2 t0h = __hfma2(h2hi(h02), uyh[0], __hmul2(h2hi(h12), wyh[0]));
            __half2 t1l = __hfma2(h2lo(h03), uyh[0], __hmul2(h2lo(h13), wyh[0]));
            __half2 t1h = __hfma2(h2hi(h03), uyh[0], __hmul2(h2hi(h13), wyh[0]));
            __half2 vl  = __hfma2(t0l, uxh[1], __hmul2(t1l, wxh[1]));
            __half2 vh  = __hfma2(t0h, uxh[1], __hmul2(t1h, wxh[1]));
            bl = __hmax2(bl, vl);
            bh = __hmax2(bh, vh);
        }
        {   // ky1 kx0: rows h20 (y0) / h30 (y1)
            __half2 t0l = __hfma2(h2lo(h20), uyh[1], __hmul2(h2lo(h30), wyh[1]));
            __half2 t0h = __hfma2(h2hi(h20), uyh[1], __hmul2(h2hi(h30), wyh[1]));
            __half2 t1l = __hfma2(h2lo(h21), uyh[1], __hmul2(h2lo(h31), wyh[1]));
            __half2 t1h = __hfma2(h2hi(h21), uyh[1], __hmul2(h2hi(h31), wyh[1]));
            __half2 vl  = __hfma2(t0l, uxh[0], __hmul2(t1l, wxh[0]));
            __half2 vh  = __hfma2(t0h, uxh[0], __hmul2(t1h, wxh[0]));
            bl = __hmax2(bl, vl);
            bh = __hmax2(bh, vh);
        }
        {   // ky1 kx1
            __half2 t0l = __hfma2(h2lo(h22), uyh[1], __hmul2(h2lo(h32), wyh[1]));
            __half2 t0h = __hfma2(h2hi(h22), uyh[1], __hmul2(h2hi(h32), wyh[1]));
            __half2 t1l = __hfma2(h2lo(h23), uyh[1], __hmul2(h2lo(h33), wyh[1]));
            __half2 t1h = __hfma2(h2hi(h23), uyh[1], __hmul2(h2hi(h33), wyh[1]));
            __half2 vl  = __hfma2(t0l, uxh[1], __hmul2(t1l, wxh[1]));
            __half2 vh  = __hfma2(t0h, uxh[1], __hmul2(t1h, wxh[1]));
            bl = __hmax2(bl, vl);
            bh = __hmax2(bh, vh);
        }

        float4 res;
        res.x = __low2float(bl);
        res.y = __high2float(bl);
        res.z = __low2float(bh);
        res.w = __high2float(bh);
        outp[pw * CPIX] = res;
    }
}

extern "C" void kernel_launch(void* const* d_in, const int* in_sizes, int n_in,
                              void* d_out, int out_size) {
    const float* fm   = (const float*)d_in[0];   // (2,50,50,512) f32
    const float* rois = (const float*)d_in[1];   // (2,128,4) f32
    float* out = (float*)d_out;                  // (256,7,7,512) f32

    conv_kernel<<<1250, 256>>>((const float4*)fm);       // 320,000 threads exact
    roi_pool_kernel<<<NROI * POOLED, 128>>>(rois, out);  // 1792 blocks
}